// round 15
// baseline (speedup 1.0000x reference)
#include <cuda_runtime.h>
#include <cuda_fp16.h>
#include <math.h>
#include <stdint.h>

// CTRNN B=8192, N=512, K=512, 6 unfolds + 1 precompute GEMM.
// R15: ALL 7 GEMMs FUSED into one persistent launch with software grid
//      barriers (256 CTAs co-resident by construction: regs<=128, smem 96KB,
//      2 CTAs/SM => 296 slots). Inter-unfold state stays L2-resident.
//      Cross-CTA re-read data uses .cg/.ldcg (L1-bypass) for coherence.
// Per-GEMM core unchanged from R13 (best): single-pass fp16 HMMA, fp16 P,
// 3-stage cp.async ring, smem-staged coalesced epilogue, tanh.approx.

#define BB 8192
#define NN 512
#define KK 512
#define NCTA 256

// ---- scratch (device globals; no allocs allowed) ----
__device__ __half g_A16[BB * KK];        // fp16(inputs)
__device__ __half g_S16[2][BB * NN];     // fp16 state operand (ping-pong)
__device__ float  g_S32[2][BB * NN];     // fp32 state (ping-pong)
__device__ __half g_P16[BB * NN];        // fp16 P
__device__ __half g_WtIn16[NN * KK];     // Wt[n][k] = W[k][n]
__device__ __half g_WtRec16[NN * KK];    // Wt[n][k] = W[k+512][n]

// ---- grid barrier state ----
__device__ unsigned g_bar_count;
__device__ volatile unsigned g_bar_phase;

// ---- helpers ----
__device__ __forceinline__ uint32_t smem_u32(const void* p) {
    uint32_t a;
    asm("{ .reg .u64 t; cvta.to.shared.u64 t, %1; cvt.u32.u64 %0, t; }" : "=r"(a) : "l"(p));
    return a;
}
__device__ __forceinline__ void cp_async16(uint32_t dst, const void* src) {
    asm volatile("cp.async.cg.shared.global [%0], [%1], 16;" :: "r"(dst), "l"(src));
}
#define CP_COMMIT() asm volatile("cp.async.commit_group;" ::: "memory")
#define CP_WAIT1()  asm volatile("cp.async.wait_group 1;" ::: "memory")
#define CP_WAIT0()  asm volatile("cp.async.wait_group 0;" ::: "memory")

__device__ __forceinline__ float tanh_approx(float x) {
    float y;
    asm("tanh.approx.f32 %0, %1;" : "=f"(y) : "f"(x));
    return y;
}
__device__ __forceinline__ void ldm4(uint32_t* r, uint32_t addr) {
    asm volatile("ldmatrix.sync.aligned.m8n8.x4.shared.b16 {%0,%1,%2,%3}, [%4];"
                 : "=r"(r[0]), "=r"(r[1]), "=r"(r[2]), "=r"(r[3]) : "r"(addr));
}
__device__ __forceinline__ void mma16816(float* d, const uint32_t* a, uint32_t b0, uint32_t b1) {
    asm volatile(
        "mma.sync.aligned.m16n8k16.row.col.f32.f16.f16.f32 "
        "{%0,%1,%2,%3}, {%4,%5,%6,%7}, {%8,%9}, {%0,%1,%2,%3};"
        : "+f"(d[0]), "+f"(d[1]), "+f"(d[2]), "+f"(d[3])
        : "r"(a[0]), "r"(a[1]), "r"(a[2]), "r"(a[3]), "r"(b0), "r"(b1));
}

// grid barrier: all NCTA CTAs co-resident (guaranteed by launch config).
__device__ __forceinline__ void grid_barrier(unsigned expected, int tid) {
    __threadfence();            // flush this CTA's writes
    __syncthreads();            // all threads in CTA arrived
    if (tid == 0) {
        unsigned t = atomicAdd(&g_bar_count, 1u);
        if (t == NCTA - 1) {
            g_bar_count = 0;
            __threadfence();
            g_bar_phase = expected;   // release
        } else {
            while (g_bar_phase != expected) { __nanosleep(64); }
        }
    }
    __syncthreads();
    __threadfence();
}

// ---- geometry ----
#define TM 128
#define TN 128
#define TKC 64                 // K-chunk (fp16) = 128B rows
#define NCHUNK (KK / TKC)      // 8
#define NSTAGE 3
#define TILE_SZ (128 * 128)    // 16384 bytes (A or B tile)
#define BUF_B (2 * TILE_SZ)    // 32768 (A then B)
#define STG_STRIDE 132
#define DSMEM (NSTAGE * BUF_B) // 98304 (>= staging 67584)

// fill a 128-row x 64-fp16 tile (128B swizzled rows) from [row0..][kc..kc+64)
__device__ __forceinline__ void fill_tile(uint32_t sbase, const __half* g,
                                          int row0, int kc, int tid) {
    #pragma unroll
    for (int c = tid; c < 1024; c += 256) {
        int r = c >> 3, q = c & 7;
        uint32_t dst = sbase + (uint32_t)(r * 128 + ((q ^ (r & 7)) * 16));
        cp_async16(dst, g + (size_t)(row0 + r) * 512 + kc + q * 8);
    }
}

__global__ void reset_barrier() { g_bar_count = 0; g_bar_phase = 0; }

__global__ __launch_bounds__(256, 2)
void ctrnn_fused(const __half* __restrict__ a16,
                 const __half* __restrict__ wtin,
                 const __half* __restrict__ wtrec,
                 __half* __restrict__ p16,
                 const float* __restrict__ state0,
                 const float* __restrict__ bias,
                 __half* __restrict__ s16_0, __half* __restrict__ s16_1,
                 float* __restrict__ s32_0, float* __restrict__ s32_1,
                 float* __restrict__ out, float* __restrict__ out2)
{
    extern __shared__ char dsm_raw[];
    const uint32_t dsm = smem_u32(dsm_raw);
    float* const stg = (float*)dsm_raw;

    const int tid = threadIdx.x;
    const int w = tid >> 5;
    const int lane = tid & 31;
    const int warpM = w >> 2;
    const int warpN = w & 3;
    const int br = (blockIdx.x >> 2) * TM;   // 64 row blocks
    const int bc = (blockIdx.x & 3) * TN;    // 4 col blocks

    // per-lane swizzled ldmatrix base offsets (k16 group g => XOR g*32)
    uint32_t abase[4], bbase[2];
    {
        const int arl = lane & 15, aq = lane >> 4;
        #pragma unroll
        for (int mi = 0; mi < 4; mi++) {
            int row = warpM * 64 + mi * 16 + arl;
            abase[mi] = (uint32_t)(row * 128 + ((aq ^ (row & 7)) * 16));
        }
        const int brl = (lane >> 4) * 8 + (lane & 7), bq = (lane >> 3) & 1;
        #pragma unroll
        for (int p = 0; p < 2; p++) {
            int row = warpN * 32 + p * 16 + brl;
            bbase[p] = (uint32_t)(row * 128 + ((bq ^ (row & 7)) * 16));
        }
    }

    const int tg = lane >> 2;
    const int tp = lane & 3;

    #pragma unroll 1
    for (int u = 0; u < 7; u++) {
        const int mode = (u == 0) ? 0 : 1;
        const __half* A  = (u == 0) ? a16 : ((u & 1) ? s16_0 : s16_1);
        const __half* Wt = (u == 0) ? wtin : wtrec;
        const float* S32in = (u == 1) ? state0 : ((u & 1) ? s32_1 : s32_0);
        __half* S16out = (u == 6) ? nullptr : ((u & 1) ? s16_1 : s16_0);
        float* S32out = (u == 6) ? out : ((u & 1) ? s32_0 : s32_1);
        float* S32out2 = (u == 6) ? out2 : nullptr;

        float acc[4][4][4];
        #pragma unroll
        for (int mi = 0; mi < 4; mi++)
            #pragma unroll
            for (int ni = 0; ni < 4; ni++)
                #pragma unroll
                for (int q = 0; q < 4; q++) acc[mi][ni][q] = 0.0f;

        // prologue: fill stages 0,1
        #pragma unroll
        for (int s = 0; s < 2; s++) {
            uint32_t sb = dsm + s * BUF_B;
            fill_tile(sb,           A,  br, s * TKC, tid);
            fill_tile(sb + TILE_SZ, Wt, bc, s * TKC, tid);
            CP_COMMIT();
        }

        int stage = 0, fstage = 2;
        for (int i = 0; i < NCHUNK; i++) {
            if (i == NCHUNK - 1) { CP_WAIT0(); } else { CP_WAIT1(); }
            __syncthreads();
            if (i + 2 < NCHUNK) {
                uint32_t nb = dsm + fstage * BUF_B;
                fill_tile(nb,           A,  br, (i + 2) * TKC, tid);
                fill_tile(nb + TILE_SZ, Wt, bc, (i + 2) * TKC, tid);
                CP_COMMIT();
            }

            const uint32_t sb = dsm + stage * BUF_B;
            #pragma unroll
            for (int g = 0; g < 4; g++) {
                const uint32_t kx = (uint32_t)(g * 32);
                uint32_t a[4][4], b[2][4];
                #pragma unroll
                for (int mi = 0; mi < 4; mi++)
                    ldm4(a[mi], (sb + abase[mi]) ^ kx);
                #pragma unroll
                for (int p = 0; p < 2; p++)
                    ldm4(b[p], (sb + TILE_SZ + bbase[p]) ^ kx);
                #pragma unroll
                for (int mi = 0; mi < 4; mi++)
                    #pragma unroll
                    for (int ni = 0; ni < 4; ni++) {
                        const uint32_t* B = b[ni >> 1];
                        const int o = (ni & 1) * 2;
                        mma16816(acc[mi][ni], a[mi], B[o], B[o + 1]);
                    }
            }
            stage = (stage + 1 == NSTAGE) ? 0 : stage + 1;
            fstage = (fstage + 1 == NSTAGE) ? 0 : fstage + 1;
        }

        // ---- epilogue: stage acc to smem, coalesced linear pass ----
        __syncthreads();
        #pragma unroll
        for (int mi = 0; mi < 4; mi++) {
            #pragma unroll
            for (int h = 0; h < 2; h++) {
                const int r = warpM * 64 + mi * 16 + tg + h * 8;
                #pragma unroll
                for (int ni = 0; ni < 4; ni++) {
                    const int c = warpN * 32 + ni * 8 + tp * 2;
                    *(float2*)&stg[r * STG_STRIDE + c] =
                        make_float2(acc[mi][ni][h * 2 + 0], acc[mi][ni][h * 2 + 1]);
                }
            }
        }
        __syncthreads();

        #pragma unroll
        for (int it = 0; it < 16; it++) {
            const int idx = it * 256 + tid;
            const int r = idx >> 5;
            const int cq = (idx & 31) * 4;
            const float4 v = *(const float4*)&stg[r * STG_STRIDE + cq];
            const size_t off = (size_t)(br + r) * NN + bc + cq;

            if (mode == 0) {
                float4 bv = *(const float4*)&bias[bc + cq];
                __half2 h0, h1;
                h0.x = __float2half(v.x + bv.x); h0.y = __float2half(v.y + bv.y);
                h1.x = __float2half(v.z + bv.z); h1.y = __float2half(v.w + bv.w);
                uint2 o;
                o.x = *(uint32_t*)&h0; o.y = *(uint32_t*)&h1;
                *(uint2*)(p16 + off) = o;
            } else {
                // L1-bypass loads: these buffers are rewritten by OTHER CTAs
                // between unfolds; stale L1 hits would corrupt.
                uint2 praw = __ldcg((const uint2*)(p16 + off));
                __half2 p0 = *(__half2*)&praw.x, p1 = *(__half2*)&praw.y;
                float4 sv = __ldcg((const float4*)&S32in[off]);
                float f0 = tanh_approx(__half2float(p0.x) + v.x);
                float f1 = tanh_approx(__half2float(p0.y) + v.y);
                float f2 = tanh_approx(__half2float(p1.x) + v.z);
                float f3 = tanh_approx(__half2float(p1.y) + v.w);
                float4 ns;
                ns.x = sv.x + 0.1f * (f0 - sv.x);
                ns.y = sv.y + 0.1f * (f1 - sv.y);
                ns.z = sv.z + 0.1f * (f2 - sv.z);
                ns.w = sv.w + 0.1f * (f3 - sv.w);
                *(float4*)&S32out[off] = ns;
                if (S16out) {
                    __half2 h0, h1;
                    h0.x = __float2half(ns.x); h0.y = __float2half(ns.y);
                    h1.x = __float2half(ns.z); h1.y = __float2half(ns.w);
                    uint2 o;
                    o.x = *(uint32_t*)&h0; o.y = *(uint32_t*)&h1;
                    *(uint2*)(S16out + off) = o;
                }
                if (S32out2) *(float4*)&S32out2[off] = ns;
            }
        }

        if (u < 6) grid_barrier((unsigned)(u + 1), tid);
    }
}

// ---- prep: fp32 -> fp16 for inputs and state ----
#define SPLIT_VECS (BB * KK / 4)

__global__ void split_kernel(const float* __restrict__ in, const float* __restrict__ st,
                             __half* __restrict__ a16, __half* __restrict__ s16)
{
    int t = blockIdx.x * blockDim.x + threadIdx.x;
    if (t >= SPLIT_VECS) return;
    size_t i = (size_t)t * 4;
    float4 vi = *(const float4*)&in[i];
    float4 vs = *(const float4*)&st[i];
    __half2 a0, a1, s0, s1;
    a0.x = __float2half(vi.x); a0.y = __float2half(vi.y);
    a1.x = __float2half(vi.z); a1.y = __float2half(vi.w);
    s0.x = __float2half(vs.x); s0.y = __float2half(vs.y);
    s1.x = __float2half(vs.z); s1.y = __float2half(vs.w);
    *(__half2*)(a16 + i)     = a0;
    *(__half2*)(a16 + i + 2) = a1;
    *(__half2*)(s16 + i)     = s0;
    *(__half2*)(s16 + i + 2) = s1;
}

// ---- prep: transpose W -> Wt[n][k] fp16 (both halves) ----
__global__ void wprep_kernel(const float* __restrict__ W,
                             __half* __restrict__ WtIn, __half* __restrict__ WtRec)
{
    int t = blockIdx.x * blockDim.x + threadIdx.x;
    if (t >= NN * KK) return;
    int k = t / NN, n = t % NN;
    int h = blockIdx.y;
    float v = W[(size_t)(k + h * KK) * NN + n];
    size_t o = (size_t)n * KK + k;
    if (h == 0) WtIn[o]  = __float2half(v);
    else        WtRec[o] = __float2half(v);
}

extern "C" void kernel_launch(void* const* d_in, const int* in_sizes, int n_in,
                              void* d_out, int out_size)
{
    const float* inputs = (const float*)d_in[0];
    const float* state  = (const float*)d_in[1];
    const float* W      = (const float*)d_in[2];
    const float* bias   = (const float*)d_in[3];
    float* out = (float*)d_out;
    float* out2 = (out_size >= 2 * BB * NN) ? (out + (size_t)BB * NN) : nullptr;

    __half *a16, *s16_0, *s16_1, *wtin, *wtrec, *p16;
    float *s32_0, *s32_1;
    cudaGetSymbolAddress((void**)&a16,   g_A16);
    cudaGetSymbolAddress((void**)&s16_0, g_S16);  s16_1 = s16_0 + (size_t)BB * NN;
    cudaGetSymbolAddress((void**)&s32_0, g_S32);  s32_1 = s32_0 + (size_t)BB * NN;
    cudaGetSymbolAddress((void**)&p16,   g_P16);
    cudaGetSymbolAddress((void**)&wtin,  g_WtIn16);
    cudaGetSymbolAddress((void**)&wtrec, g_WtRec16);

    cudaFuncSetAttribute(ctrnn_fused, cudaFuncAttributeMaxDynamicSharedMemorySize, DSMEM);

    reset_barrier<<<1, 1>>>();
    split_kernel<<<(SPLIT_VECS + 255) / 256, 256>>>(inputs, state, a16, s16_0);
    wprep_kernel<<<dim3((NN * KK + 255) / 256, 2), 256>>>(W, wtin, wtrec);

    ctrnn_fused<<<NCTA, 256, DSMEM>>>(a16, wtin, wtrec, p16, state, bias,
                                      s16_0, s16_1, s32_0, s32_1, out, out2);
}

// round 16
// speedup vs baseline: 1.0542x; 1.0542x over previous
#include <cuda_runtime.h>
#include <cuda_fp16.h>
#include <math.h>
#include <stdint.h>

// CTRNN B=8192, N=512, K=512, 6 unfolds + 1 precompute GEMM.
// R16: fused persistent kernel with PER-ROW-GROUP (4-CTA) barriers instead of
//      a global 256-CTA barrier, + W prologue prefetch issued BEFORE the
//      barrier (W is unfold-invariant). Unfold u+1's A tile (rows br, all K)
//      is written only by the 4 CTAs sharing row-block br, so a 4-CTA
//      barrier is sufficient; groups pipeline past each other.
// Core per-GEMM unchanged: single-pass fp16 HMMA, fp16 P, 3-stage cp.async
// ring, smem-staged coalesced epilogue, tanh.approx.

#define BB 8192
#define NN 512
#define KK 512
#define NCTA 256
#define NGRP 64          // row groups; 4 CTAs each

// ---- scratch (device globals; no allocs allowed) ----
__device__ __half g_A16[BB * KK];
__device__ __half g_S16[2][BB * NN];
__device__ float  g_S32[2][BB * NN];
__device__ __half g_P16[BB * NN];
__device__ __half g_WtIn16[NN * KK];
__device__ __half g_WtRec16[NN * KK];

// ---- group barrier state ----
__device__ unsigned g_bar_count[NGRP];
__device__ volatile unsigned g_bar_phase[NGRP];

// ---- helpers ----
__device__ __forceinline__ uint32_t smem_u32(const void* p) {
    uint32_t a;
    asm("{ .reg .u64 t; cvta.to.shared.u64 t, %1; cvt.u32.u64 %0, t; }" : "=r"(a) : "l"(p));
    return a;
}
__device__ __forceinline__ void cp_async16(uint32_t dst, const void* src) {
    asm volatile("cp.async.cg.shared.global [%0], [%1], 16;" :: "r"(dst), "l"(src));
}
#define CP_COMMIT() asm volatile("cp.async.commit_group;" ::: "memory")
#define CP_WAIT1()  asm volatile("cp.async.wait_group 1;" ::: "memory")
#define CP_WAIT0()  asm volatile("cp.async.wait_group 0;" ::: "memory")

__device__ __forceinline__ float tanh_approx(float x) {
    float y;
    asm("tanh.approx.f32 %0, %1;" : "=f"(y) : "f"(x));
    return y;
}
__device__ __forceinline__ void ldm4(uint32_t* r, uint32_t addr) {
    asm volatile("ldmatrix.sync.aligned.m8n8.x4.shared.b16 {%0,%1,%2,%3}, [%4];"
                 : "=r"(r[0]), "=r"(r[1]), "=r"(r[2]), "=r"(r[3]) : "r"(addr));
}
__device__ __forceinline__ void mma16816(float* d, const uint32_t* a, uint32_t b0, uint32_t b1) {
    asm volatile(
        "mma.sync.aligned.m16n8k16.row.col.f32.f16.f16.f32 "
        "{%0,%1,%2,%3}, {%4,%5,%6,%7}, {%8,%9}, {%0,%1,%2,%3};"
        : "+f"(d[0]), "+f"(d[1]), "+f"(d[2]), "+f"(d[3])
        : "r"(a[0]), "r"(a[1]), "r"(a[2]), "r"(a[3]), "r"(b0), "r"(b1));
}

// 4-CTA row-group barrier (all CTAs co-resident; deadlock-free).
__device__ __forceinline__ void group_barrier(int grp, unsigned expected, int tid) {
    __threadfence();            // release this CTA's epilogue writes
    __syncthreads();
    if (tid == 0) {
        unsigned t = atomicAdd(&g_bar_count[grp], 1u);
        if (t == 3u) {
            g_bar_count[grp] = 0u;
            __threadfence();
            g_bar_phase[grp] = expected;
        } else {
            while (g_bar_phase[grp] != expected) { __nanosleep(32); }
        }
    }
    __syncthreads();
    __threadfence();            // acquire
}

// ---- geometry ----
#define TM 128
#define TN 128
#define TKC 64
#define NCHUNK (KK / TKC)      // 8
#define NSTAGE 3
#define TILE_SZ (128 * 128)    // 16384
#define BUF_B (2 * TILE_SZ)    // 32768 (A then W)
#define STG_STRIDE 132
#define DSMEM (NSTAGE * BUF_B) // 98304

__device__ __forceinline__ void fill_tile(uint32_t sbase, const __half* g,
                                          int row0, int kc, int tid) {
    #pragma unroll
    for (int c = tid; c < 1024; c += 256) {
        int r = c >> 3, q = c & 7;
        uint32_t dst = sbase + (uint32_t)(r * 128 + ((q ^ (r & 7)) * 16));
        cp_async16(dst, g + (size_t)(row0 + r) * 512 + kc + q * 8);
    }
}
// half-size fill: one tile spread over 256 threads, 4 chunks each
__device__ __forceinline__ void fill_tile_half(uint32_t sbase, const __half* g,
                                               int row0, int kc, int tid, int part) {
    #pragma unroll
    for (int j = 0; j < 2; j++) {
        int c = part * 512 + j * 256 + tid;
        int r = c >> 3, q = c & 7;
        uint32_t dst = sbase + (uint32_t)(r * 128 + ((q ^ (r & 7)) * 16));
        cp_async16(dst, g + (size_t)(row0 + r) * 512 + kc + q * 8);
    }
}

__global__ void reset_barrier() {
    int t = threadIdx.x;
    if (t < NGRP) { g_bar_count[t] = 0u; g_bar_phase[t] = 0u; }
}

__global__ __launch_bounds__(256, 2)
void ctrnn_fused(const __half* __restrict__ a16,
                 const __half* __restrict__ wtin,
                 const __half* __restrict__ wtrec,
                 __half* __restrict__ p16,
                 const float* __restrict__ state0,
                 const float* __restrict__ bias,
                 __half* __restrict__ s16_0, __half* __restrict__ s16_1,
                 float* __restrict__ s32_0, float* __restrict__ s32_1,
                 float* __restrict__ out, float* __restrict__ out2)
{
    extern __shared__ char dsm_raw[];
    const uint32_t dsm = smem_u32(dsm_raw);
    float* const stg = (float*)dsm_raw;

    const int tid = threadIdx.x;
    const int w = tid >> 5;
    const int lane = tid & 31;
    const int warpM = w >> 2;
    const int warpN = w & 3;
    const int grp = blockIdx.x >> 2;        // row group
    const int br = grp * TM;
    const int bc = (blockIdx.x & 3) * TN;

    uint32_t abase[4], bbase[2];
    {
        const int arl = lane & 15, aq = lane >> 4;
        #pragma unroll
        for (int mi = 0; mi < 4; mi++) {
            int row = warpM * 64 + mi * 16 + arl;
            abase[mi] = (uint32_t)(row * 128 + ((aq ^ (row & 7)) * 16));
        }
        const int brl = (lane >> 4) * 8 + (lane & 7), bq = (lane >> 3) & 1;
        #pragma unroll
        for (int p = 0; p < 2; p++) {
            int row = warpN * 32 + p * 16 + brl;
            bbase[p] = (uint32_t)(row * 128 + ((bq ^ (row & 7)) * 16));
        }
    }
    const int tg = lane >> 2;
    const int tp = lane & 3;

    // u=0 prologue: A + W for stages 0,1 (one commit per stage)
    #pragma unroll
    for (int s = 0; s < 2; s++) {
        uint32_t sb = dsm + s * BUF_B;
        fill_tile(sb,           a16,  br, s * TKC, tid);
        fill_tile(sb + TILE_SZ, wtin, bc, s * TKC, tid);
        CP_COMMIT();
    }
    int pending_pre = 2;    // commit-groups covering the current prologue

    #pragma unroll 1
    for (int u = 0; u < 7; u++) {
        const int mode = (u == 0) ? 0 : 1;
        const __half* A  = (u == 0) ? a16 : ((u & 1) ? s16_0 : s16_1);
        const __half* Wt = (u == 0) ? wtin : wtrec;
        const float* S32in = (u == 1) ? state0 : ((u & 1) ? s32_1 : s32_0);
        __half* S16out = (u == 6) ? nullptr : ((u & 1) ? s16_1 : s16_0);
        float* S32out = (u == 6) ? out : ((u & 1) ? s32_0 : s32_1);
        float* S32out2 = (u == 6) ? out2 : nullptr;

        // complete prologue for this unfold: A fills for stages 0,1 (W already
        // in flight for u>=1; for u==0 everything was filled above).
        if (u > 0) {
            fill_tile(dsm,         A, br, 0,   tid);  CP_COMMIT();
            fill_tile(dsm + BUF_B, A, br, TKC, tid);  CP_COMMIT();
            pending_pre += 2;
        }
        (void)pending_pre;

        float acc[4][4][4];
        #pragma unroll
        for (int mi = 0; mi < 4; mi++)
            #pragma unroll
            for (int ni = 0; ni < 4; ni++)
                #pragma unroll
                for (int q = 0; q < 4; q++) acc[mi][ni][q] = 0.0f;

        int stage = 0, fstage = 2;
        for (int i = 0; i < NCHUNK; i++) {
            if (i == NCHUNK - 1) { CP_WAIT0(); } else { CP_WAIT1(); }
            __syncthreads();
            if (i + 2 < NCHUNK) {
                uint32_t nb = dsm + fstage * BUF_B;
                fill_tile(nb,           A,  br, (i + 2) * TKC, tid);
                fill_tile(nb + TILE_SZ, Wt, bc, (i + 2) * TKC, tid);
                CP_COMMIT();
            }

            const uint32_t sb = dsm + stage * BUF_B;
            #pragma unroll
            for (int g = 0; g < 4; g++) {
                const uint32_t kx = (uint32_t)(g * 32);
                uint32_t a[4][4], b[2][4];
                #pragma unroll
                for (int mi = 0; mi < 4; mi++)
                    ldm4(a[mi], (sb + abase[mi]) ^ kx);
                #pragma unroll
                for (int p = 0; p < 2; p++)
                    ldm4(b[p], (sb + TILE_SZ + bbase[p]) ^ kx);
                #pragma unroll
                for (int mi = 0; mi < 4; mi++)
                    #pragma unroll
                    for (int ni = 0; ni < 4; ni++) {
                        const uint32_t* B = b[ni >> 1];
                        const int o = (ni & 1) * 2;
                        mma16816(acc[mi][ni], a[mi], B[o], B[o + 1]);
                    }
            }
            stage = (stage + 1 == NSTAGE) ? 0 : stage + 1;
            fstage = (fstage + 1 == NSTAGE) ? 0 : fstage + 1;
        }

        // ---- epilogue: stage acc to smem, coalesced linear pass ----
        __syncthreads();
        #pragma unroll
        for (int mi = 0; mi < 4; mi++) {
            #pragma unroll
            for (int h = 0; h < 2; h++) {
                const int r = warpM * 64 + mi * 16 + tg + h * 8;
                #pragma unroll
                for (int ni = 0; ni < 4; ni++) {
                    const int c = warpN * 32 + ni * 8 + tp * 2;
                    *(float2*)&stg[r * STG_STRIDE + c] =
                        make_float2(acc[mi][ni][h * 2 + 0], acc[mi][ni][h * 2 + 1]);
                }
            }
        }
        __syncthreads();

        #pragma unroll
        for (int it = 0; it < 16; it++) {
            const int idx = it * 256 + tid;
            const int r = idx >> 5;
            const int cq = (idx & 31) * 4;
            const float4 v = *(const float4*)&stg[r * STG_STRIDE + cq];
            const size_t off = (size_t)(br + r) * NN + bc + cq;

            if (mode == 0) {
                float4 bv = *(const float4*)&bias[bc + cq];
                __half2 h0, h1;
                h0.x = __float2half(v.x + bv.x); h0.y = __float2half(v.y + bv.y);
                h1.x = __float2half(v.z + bv.z); h1.y = __float2half(v.w + bv.w);
                uint2 o;
                o.x = *(uint32_t*)&h0; o.y = *(uint32_t*)&h1;
                *(uint2*)(p16 + off) = o;
            } else {
                uint2 praw = __ldcg((const uint2*)(p16 + off));
                __half2 p0 = *(__half2*)&praw.x, p1 = *(__half2*)&praw.y;
                float4 sv = __ldcg((const float4*)&S32in[off]);
                float f0 = tanh_approx(__half2float(p0.x) + v.x);
                float f1 = tanh_approx(__half2float(p0.y) + v.y);
                float f2 = tanh_approx(__half2float(p1.x) + v.z);
                float f3 = tanh_approx(__half2float(p1.y) + v.w);
                float4 ns;
                ns.x = sv.x + 0.1f * (f0 - sv.x);
                ns.y = sv.y + 0.1f * (f1 - sv.y);
                ns.z = sv.z + 0.1f * (f2 - sv.z);
                ns.w = sv.w + 0.1f * (f3 - sv.w);
                *(float4*)&S32out[off] = ns;
                if (S16out) {
                    __half2 h0, h1;
                    h0.x = __float2half(ns.x); h0.y = __float2half(ns.y);
                    h1.x = __float2half(ns.z); h1.y = __float2half(ns.w);
                    uint2 o;
                    o.x = *(uint32_t*)&h0; o.y = *(uint32_t*)&h1;
                    *(uint2*)(S16out + off) = o;
                }
                if (S32out2) *(float4*)&S32out2[off] = ns;
            }
        }

        if (u < 6) {
            // stg reads done; safe to overwrite smem. Prefetch next unfold's
            // W prologue (unfold-invariant -> no dependency on the barrier).
            __syncthreads();
            fill_tile(dsm + TILE_SZ,         wtrec, bc, 0,   tid);
            fill_tile(dsm + BUF_B + TILE_SZ, wtrec, bc, TKC, tid);
            CP_COMMIT();
            pending_pre = 1;
            // 4-CTA row-group barrier: next unfold's A rows depend only on
            // this group's epilogue writes.
            group_barrier(grp, (unsigned)(u + 1), tid);
        }
    }
}

// ---- prep kernels ----
#define SPLIT_VECS (BB * KK / 4)

__global__ void split_kernel(const float* __restrict__ in, const float* __restrict__ st,
                             __half* __restrict__ a16, __half* __restrict__ s16)
{
    int t = blockIdx.x * blockDim.x + threadIdx.x;
    if (t >= SPLIT_VECS) return;
    size_t i = (size_t)t * 4;
    float4 vi = *(const float4*)&in[i];
    float4 vs = *(const float4*)&st[i];
    __half2 a0, a1, s0, s1;
    a0.x = __float2half(vi.x); a0.y = __float2half(vi.y);
    a1.x = __float2half(vi.z); a1.y = __float2half(vi.w);
    s0.x = __float2half(vs.x); s0.y = __float2half(vs.y);
    s1.x = __float2half(vs.z); s1.y = __float2half(vs.w);
    *(__half2*)(a16 + i)     = a0;
    *(__half2*)(a16 + i + 2) = a1;
    *(__half2*)(s16 + i)     = s0;
    *(__half2*)(s16 + i + 2) = s1;
}

__global__ void wprep_kernel(const float* __restrict__ W,
                             __half* __restrict__ WtIn, __half* __restrict__ WtRec)
{
    int t = blockIdx.x * blockDim.x + threadIdx.x;
    if (t >= NN * KK) return;
    int k = t / NN, n = t % NN;
    int h = blockIdx.y;
    float v = W[(size_t)(k + h * KK) * NN + n];
    size_t o = (size_t)n * KK + k;
    if (h == 0) WtIn[o]  = __float2half(v);
    else        WtRec[o] = __float2half(v);
}

extern "C" void kernel_launch(void* const* d_in, const int* in_sizes, int n_in,
                              void* d_out, int out_size)
{
    const float* inputs = (const float*)d_in[0];
    const float* state  = (const float*)d_in[1];
    const float* W      = (const float*)d_in[2];
    const float* bias   = (const float*)d_in[3];
    float* out = (float*)d_out;
    float* out2 = (out_size >= 2 * BB * NN) ? (out + (size_t)BB * NN) : nullptr;

    __half *a16, *s16_0, *s16_1, *wtin, *wtrec, *p16;
    float *s32_0, *s32_1;
    cudaGetSymbolAddress((void**)&a16,   g_A16);
    cudaGetSymbolAddress((void**)&s16_0, g_S16);  s16_1 = s16_0 + (size_t)BB * NN;
    cudaGetSymbolAddress((void**)&s32_0, g_S32);  s32_1 = s32_0 + (size_t)BB * NN;
    cudaGetSymbolAddress((void**)&p16,   g_P16);
    cudaGetSymbolAddress((void**)&wtin,  g_WtIn16);
    cudaGetSymbolAddress((void**)&wtrec, g_WtRec16);

    cudaFuncSetAttribute(ctrnn_fused, cudaFuncAttributeMaxDynamicSharedMemorySize, DSMEM);

    reset_barrier<<<1, 64>>>();
    split_kernel<<<(SPLIT_VECS + 255) / 256, 256>>>(inputs, state, a16, s16_0);
    wprep_kernel<<<dim3((NN * KK + 255) / 256, 2), 256>>>(W, wtin, wtrec);

    ctrnn_fused<<<NCTA, 256, DSMEM>>>(a16, wtin, wtrec, p16, state, bias,
                                      s16_0, s16_1, s32_0, s32_1, out, out2);
}